// round 3
// baseline (speedup 1.0000x reference)
#include <cuda_runtime.h>
#include <cstdint>
#include <math.h>

#define TT 128
#define BB 32
#define HH 256
#define II 256
#define G4 1024   // 4*H
#define CL 4      // CTAs per cluster
#define BPC 2     // batch elements per cluster
#define NTH 512
#define SLOTS (TT / CL)   // 32 history slots per rank per batch

// Scratch for hoisted input projection: xproj[t][b][r] = emb@W_ih^T + b_ih + b_hh
__device__ float g_xproj[(size_t)TT * BB * G4];  // 16 MB

// ---------------------------------------------------------------------------
// Kernel A: xproj = emb @ W_ih^T + (b_ih + b_hh)   (M=4096, N=1024, K=256)
// ---------------------------------------------------------------------------
__global__ void __launch_bounds__(256) xproj_kernel(
    const float* __restrict__ emb, const float* __restrict__ W_ih,
    const float* __restrict__ b_ih, const float* __restrict__ b_hh)
{
    __shared__ float As[64][65];
    __shared__ float Bs[64][65];
    const int K = II;
    const int bm = blockIdx.x * 64, bn = blockIdx.y * 64;
    const int tx = threadIdx.x & 15, ty = threadIdx.x >> 4;
    float acc[4][4] = {};

    for (int k0 = 0; k0 < K; k0 += 64) {
        for (int i = threadIdx.x; i < 64 * 64; i += 256) {
            int r = i >> 6, cc = i & 63;
            As[r][cc] = emb[(size_t)(bm + r) * K + k0 + cc];
            Bs[r][cc] = W_ih[(size_t)(bn + r) * K + k0 + cc];
        }
        __syncthreads();
        #pragma unroll
        for (int k = 0; k < 64; k++) {
            float a[4], bv[4];
            #pragma unroll
            for (int i = 0; i < 4; i++) a[i] = As[ty * 4 + i][k];
            #pragma unroll
            for (int j = 0; j < 4; j++) bv[j] = Bs[tx * 4 + j][k];
            #pragma unroll
            for (int i = 0; i < 4; i++)
                #pragma unroll
                for (int j = 0; j < 4; j++)
                    acc[i][j] += a[i] * bv[j];
        }
        __syncthreads();
    }
    #pragma unroll
    for (int i = 0; i < 4; i++)
        #pragma unroll
        for (int j = 0; j < 4; j++) {
            int r = bm + ty * 4 + i, cI = bn + tx * 4 + j;
            g_xproj[(size_t)r * G4 + cI] = acc[i][j] + b_ih[cI] + b_hh[cI];
        }
}

// ---------------------------------------------------------------------------
// DSMEM / mbarrier helpers
// ---------------------------------------------------------------------------
__device__ __forceinline__ uint32_t smem_u32(const void* p) {
    return (uint32_t)__cvta_generic_to_shared(p);
}
__device__ __forceinline__ uint32_t my_rank() {
    uint32_t r;
    asm("mov.u32 %0, %%cluster_ctarank;" : "=r"(r));
    return r;
}
__device__ __forceinline__ void st_cluster(uint32_t laddr, int rank, float v) {
    uint32_t ra;
    asm volatile("mapa.shared::cluster.u32 %0, %1, %2;" : "=r"(ra) : "r"(laddr), "r"(rank));
    asm volatile("st.shared::cluster.f32 [%0], %1;" :: "r"(ra), "f"(v) : "memory");
}
__device__ __forceinline__ void bar_arrive_rank(uint32_t lbar, int rank) {
    uint32_t ra;
    asm volatile("mapa.shared::cluster.u32 %0, %1, %2;" : "=r"(ra) : "r"(lbar), "r"(rank));
    asm volatile("mbarrier.arrive.release.cluster.shared::cluster.b64 _, [%0];"
                 :: "r"(ra) : "memory");
}
__device__ __forceinline__ void bar_wait(uint32_t lbar, uint32_t parity) {
    asm volatile(
        "{\n\t.reg .pred P;\n\t"
        "LW_%=:\n\t"
        "mbarrier.try_wait.parity.acquire.cluster.shared::cta.b64 P, [%0], %1, 0x989680;\n\t"
        "@P bra LD_%=;\n\t"
        "bra LW_%=;\n\t"
        "LD_%=:\n\t}"
        :: "r"(lbar), "r"(parity) : "memory");
}

// ---------------------------------------------------------------------------
// Kernel B: 4-CTA cluster handles 2 batch elements. Rank r owns:
//   - history slots s with s%4==r (for both batches)
//   - W_a rows [64r, 64r+64), W_hh rows {gate*256 + 64r + jj}
//   - j-quarter [64r, 64r+64) of the cell state
// ---------------------------------------------------------------------------
__global__ void __launch_bounds__(NTH, 1) __cluster_dims__(CL, 1, 1)
recur_kernel(
    const int*   __restrict__ lens,
    const float* __restrict__ W_hh,   // [1024, 256]
    const float* __restrict__ W_a,    // [256, 512]
    const float* __restrict__ b_a,    // [256]
    float* __restrict__ out)          // output[T,B,H] ++ h_fin[B,H] ++ c_fin[B,H]
{
    extern __shared__ float smf[];
    unsigned long long* mbar = (unsigned long long*)smf;      // 4 barriers (32 B)
    float* p    = smf + 8;
    float* bufs = p; p += BPC * SLOTS * HH;   // [g][slot][j]  64 KB
    float* hS   = p; p += BPC * HH;           // full h, replicated
    float* huS  = p; p += BPC * HH;           // combined hidden, gathered
    float* ctxp = p; p += BPC * CL * HH;      // ctx partials   8 KB
    float* cat  = p; p += BPC * 2 * HH;       // [ctx, h]
    float* sc   = p; p += BPC * TT;           // scores -> alpha in place
    float* gts  = p; p += BPC * (G4 / CL);    // my quarter's gate pre-acts
    float* cS   = p; p += BPC * (HH / CL);    // my c quarter
    float* xps  = p; p += BPC * (G4 / CL);    // staged xproj slice

    const int tid  = threadIdx.x;
    const int warp = tid >> 5, lane = tid & 31;
    const int r    = (int)my_rank();
    const int b0   = (blockIdx.x / CL) * BPC;
    const int len0 = lens[b0], len1 = lens[b0 + 1];

    const uint32_t bar_addr[4] = { smem_u32(&mbar[0]), smem_u32(&mbar[1]),
                                   smem_u32(&mbar[2]), smem_u32(&mbar[3]) };

    if (tid < BPC * HH) { hS[tid] = 0.f; huS[tid] = 0.f; }
    if (tid < BPC * (HH / CL)) cS[tid] = 0.f;
    if (tid == 0) {
        #pragma unroll
        for (int k = 0; k < 4; k++)
            asm volatile("mbarrier.init.shared.b64 [%0], %1;" :: "r"(bar_addr[k]), "r"(CL) : "memory");
        asm volatile("fence.mbarrier_init.release.cluster;" ::: "memory");
    }
    __syncthreads();
    asm volatile("barrier.cluster.arrive.aligned;" ::: "memory");
    asm volatile("barrier.cluster.wait.aligned;" ::: "memory");

    for (int t = 0; t < TT; t++) {
        const uint32_t par = (uint32_t)(t & 1);

        // ---- stage xproj slice for this step (coalesced) ----
        {
            int gb = tid >> 8, lr = tid & 255;
            int grow = (lr >> 6) * HH + 64 * r + (lr & 63);
            xps[gb * 256 + lr] = g_xproj[((size_t)t * BB + b0 + gb) * G4 + grow];
        }

        // ---- Phase 1: scores for my s-slices (both batches), broadcast ----
        if (t > 0) {
            for (int idx = warp; idx < BPC * SLOTS; idx += 16) {
                int gb = idx >> 5, slot = idx & 31, s = slot * CL + r;
                if (s < t) {
                    const float* br = &bufs[(gb * SLOTS + slot) * HH];
                    const float* hh = &hS[gb * HH];
                    float pr = 0.f;
                    #pragma unroll
                    for (int u = 0; u < HH / 32; u++)
                        pr += br[lane + 32 * u] * hh[lane + 32 * u];
                    #pragma unroll
                    for (int o = 16; o > 0; o >>= 1) pr += __shfl_xor_sync(0xffffffffu, pr, o);
                    if (lane < CL) st_cluster(smem_u32(&sc[gb * TT + s]), lane, pr);
                }
            }
        }
        __syncthreads();
        if (tid < CL) bar_arrive_rank(bar_addr[0], tid);
        bar_wait(bar_addr[0], par);                                   // B1

        // ---- Phase 2: softmax -> alpha in sc (warps 0-1), then ctx partial
        if (t > 0) {
            if (warp < BPC) {
                int gb = warp;
                float m = -1e30f;
                for (int s = lane; s < t; s += 32) m = fmaxf(m, sc[gb * TT + s]);
                #pragma unroll
                for (int o = 16; o > 0; o >>= 1) m = fmaxf(m, __shfl_xor_sync(0xffffffffu, m, o));
                float sum = 0.f;
                for (int s = lane; s < t; s += 32) {
                    float e = __expf(sc[gb * TT + s] - m);
                    sc[gb * TT + s] = e; sum += e;
                }
                #pragma unroll
                for (int o = 16; o > 0; o >>= 1) sum += __shfl_xor_sync(0xffffffffu, sum, o);
                float inv = 1.f / sum;
                for (int s = lane; s < t; s += 32) sc[gb * TT + s] *= inv;
            }
            __syncthreads();

            if (tid < BPC * (HH / 4)) {   // 128 threads, float4 per thread
                int gb = tid >> 6, q = tid & 63;
                float4 a4 = make_float4(0.f, 0.f, 0.f, 0.f);
                #pragma unroll 4
                for (int slot = 0; slot < SLOTS; slot++) {
                    int s = slot * CL + r;
                    if (s >= t) break;
                    float al = sc[gb * TT + s];
                    float4 v = *(const float4*)&bufs[(gb * SLOTS + slot) * HH + q * 4];
                    a4.x += al * v.x; a4.y += al * v.y; a4.z += al * v.z; a4.w += al * v.w;
                }
                uint32_t pa = smem_u32(&ctxp[(gb * CL + r) * HH + q * 4]);
                #pragma unroll
                for (int peer = 0; peer < CL; peer++) {
                    st_cluster(pa +  0, peer, a4.x);
                    st_cluster(pa +  4, peer, a4.y);
                    st_cluster(pa +  8, peer, a4.z);
                    st_cluster(pa + 12, peer, a4.w);
                }
            }
        }
        __syncthreads();
        if (tid < CL) bar_arrive_rank(bar_addr[1], tid);
        bar_wait(bar_addr[1], par);                                   // B2

        // ---- Phase 3: cat = [ctx, h]; combine GEMV for my 64 rows × 2 batches
        if (t > 0) {
            if (tid < BPC * HH) {
                int gb = tid >> 8, j = tid & (HH - 1);
                cat[gb * 2 * HH + j] = ctxp[(gb * CL + 0) * HH + j] + ctxp[(gb * CL + 1) * HH + j]
                                     + ctxp[(gb * CL + 2) * HH + j] + ctxp[(gb * CL + 3) * HH + j];
                cat[gb * 2 * HH + HH + j] = hS[gb * HH + j];
            }
            __syncthreads();
            {
                int gb = warp >> 3;
                int rowl = (warp & 7) * 8;
                float acc[8] = {0.f, 0.f, 0.f, 0.f, 0.f, 0.f, 0.f, 0.f};
                #pragma unroll
                for (int it = 0; it < 4; it++) {
                    float4 x = *(const float4*)&cat[gb * 2 * HH + it * 128 + lane * 4];
                    #pragma unroll
                    for (int rr = 0; rr < 8; rr++) {
                        int grow = 64 * r + rowl + rr;
                        float4 w = __ldg((const float4*)&W_a[(size_t)grow * (2 * HH) + it * 128 + lane * 4]);
                        acc[rr] += w.x * x.x + w.y * x.y + w.z * x.z + w.w * x.w;
                    }
                }
                #pragma unroll
                for (int rr = 0; rr < 8; rr++) {
                    float v = acc[rr];
                    #pragma unroll
                    for (int o = 16; o > 0; o >>= 1) v += __shfl_xor_sync(0xffffffffu, v, o);
                    int grow = 64 * r + rowl + rr;
                    if (lane < CL) {
                        float hv = tanhf(v + __ldg(&b_a[grow]));
                        st_cluster(smem_u32(&huS[gb * HH + grow]), lane, hv);
                    }
                }
            }
        } else {
            if (tid < BPC * HH) huS[tid] = hS[tid];
        }
        __syncthreads();
        if (tid < CL) bar_arrive_rank(bar_addr[2], tid);
        bar_wait(bar_addr[2], par);                                   // B3

        // ---- Phase 4: gates for my 256 W_hh rows, both batches (weight reuse)
        {
            #pragma unroll
            for (int grp = 0; grp < 2; grp++) {
                int lrb = warp * 16 + grp * 8;
                float a0[8] = {0.f, 0.f, 0.f, 0.f, 0.f, 0.f, 0.f, 0.f};
                float a1[8] = {0.f, 0.f, 0.f, 0.f, 0.f, 0.f, 0.f, 0.f};
                #pragma unroll
                for (int it = 0; it < 2; it++) {
                    float4 x0 = *(const float4*)&huS[0 * HH + it * 128 + lane * 4];
                    float4 x1 = *(const float4*)&huS[1 * HH + it * 128 + lane * 4];
                    #pragma unroll
                    for (int rr = 0; rr < 8; rr++) {
                        int lr = lrb + rr;
                        int grow = (lr >> 6) * HH + 64 * r + (lr & 63);
                        float4 w = __ldcg((const float4*)&W_hh[(size_t)grow * HH + it * 128 + lane * 4]);
                        a0[rr] += w.x * x0.x + w.y * x0.y + w.z * x0.z + w.w * x0.w;
                        a1[rr] += w.x * x1.x + w.y * x1.y + w.z * x1.z + w.w * x1.w;
                    }
                }
                #pragma unroll
                for (int rr = 0; rr < 8; rr++) {
                    float v0 = a0[rr], v1 = a1[rr];
                    #pragma unroll
                    for (int o = 16; o > 0; o >>= 1) {
                        v0 += __shfl_xor_sync(0xffffffffu, v0, o);
                        v1 += __shfl_xor_sync(0xffffffffu, v1, o);
                    }
                    if (lane == rr) {
                        int lr = lrb + rr;
                        gts[0 * 256 + lr] = v0 + xps[0 * 256 + lr];
                        gts[1 * 256 + lr] = v1 + xps[1 * 256 + lr];
                    }
                }
            }
            __syncthreads();

            // ---- cell update for my j-quarter, both batches ----
            if (tid < BPC * (HH / CL)) {
                int gb = tid >> 6, jj = tid & 63, j = 64 * r + jj;
                float ig = gts[gb * 256 + jj],        fg = gts[gb * 256 + 64 + jj];
                float gg = gts[gb * 256 + 128 + jj],  og = gts[gb * 256 + 192 + jj];
                float si = 1.f / (1.f + __expf(-ig));
                float sf = 1.f / (1.f + __expf(-fg));
                float so = 1.f / (1.f + __expf(-og));
                float cn = sf * cS[gb * 64 + jj] + si * tanhf(gg);
                float hn = so * tanhf(cn);
                cS[gb * 64 + jj] = cn;

                uint32_t ha = smem_u32(&hS[gb * HH + j]);
                #pragma unroll
                for (int peer = 0; peer < CL; peer++) st_cluster(ha, peer, hn);
                st_cluster(smem_u32(&bufs[(gb * SLOTS + (t >> 2)) * HH + j]), t & 3, hn);

                int b = b0 + gb;
                out[((size_t)t * BB + b) * HH + j] = hn;
                int ln = gb ? len1 : len0;
                if (t == ln - 1) {
                    out[(size_t)TT * BB * HH + (size_t)b * HH + j] = hn;
                    out[(size_t)TT * BB * HH + (size_t)BB * HH + (size_t)b * HH + j] = cn;
                }
            }
        }
        __syncthreads();
        if (tid < CL) bar_arrive_rank(bar_addr[3], tid);
        bar_wait(bar_addr[3], par);                                   // B4
    }
}

// ---------------------------------------------------------------------------
extern "C" void kernel_launch(void* const* d_in, const int* in_sizes, int n_in,
                              void* d_out, int out_size)
{
    const float* embs = (const float*)d_in[0];
    const int*   lens = (const int*)  d_in[1];
    const float* W_ih = (const float*)d_in[2];
    const float* W_hh = (const float*)d_in[3];
    const float* b_ih = (const float*)d_in[4];
    const float* b_hh = (const float*)d_in[5];
    const float* W_a  = (const float*)d_in[6];
    const float* b_a  = (const float*)d_in[7];
    float* out = (float*)d_out;

    const int smem_floats = 8 + BPC * SLOTS * HH + BPC * HH * 2 + BPC * CL * HH
                          + BPC * 2 * HH + BPC * TT + BPC * (G4 / CL)
                          + BPC * (HH / CL) + BPC * (G4 / CL);
    const int smem_bytes = smem_floats * (int)sizeof(float);
    cudaFuncSetAttribute(recur_kernel, cudaFuncAttributeMaxDynamicSharedMemorySize, smem_bytes);

    xproj_kernel<<<dim3((TT * BB) / 64, G4 / 64), 256>>>(embs, W_ih, b_ih, b_hh);
    recur_kernel<<<(BB / BPC) * CL, NTH, smem_bytes>>>(lens, W_hh, W_a, b_a, out);
}